// round 1
// baseline (speedup 1.0000x reference)
#include <cuda_runtime.h>

// ---------------------------------------------------------------------------
// AtlasAttention: out = (MLP(poly(clip(x@Wq))))[:, :64]
//   Shapes: x [8192, 768], Wq [768,768], W1 [256,512], W2 [512,256]
//   Algebraic reductions (exact):
//     - constant poly block folded into bias: b1eff = b1 + c0 * sum_{j<64} W1[j,:]
//     - only first 64 columns of W2 are needed
//   All math fp32; inner products use packed fma.rn.f32x2 (FFMA2).
// ---------------------------------------------------------------------------

#define TOKENS   8192          // B*S
#define HIDDEN   768
#define HD       64
#define FLATR    98304         // TOKENS * 12 heads
#define MEMH     512
#define KP       192           // poly features actually multiplied (256 - 64 folded)
#define HT_STRIDE 68           // padded [k][r] h-tile stride (16B-aligned rows)

typedef unsigned long long u64;

__device__ float g_qs[TOKENS * HIDDEN];   // clipped q scratch (25 MB)
__device__ float g_b1eff[MEMH];           // folded bias

__device__ __forceinline__ void ffma2(u64 &d, u64 a, u64 b) {
    asm("fma.rn.f32x2 %0, %1, %2, %0;" : "+l"(d) : "l"(a), "l"(b));
}
__device__ __forceinline__ u64 pack2(float x, float y) {
    u64 r; asm("mov.b64 %0, {%1, %2};" : "=l"(r) : "f"(x), "f"(y)); return r;
}
__device__ __forceinline__ float2 unpack2(u64 v) {
    float2 r; asm("mov.b64 {%0, %1}, %2;" : "=f"(r.x), "=f"(r.y) : "l"(v)); return r;
}

// ---------------------------------------------------------------------------
// Prep: fold the constant polynomial feature block into the MLP bias.
// ---------------------------------------------------------------------------
__global__ void prep_kernel(const float* __restrict__ W1,
                            const float* __restrict__ b1,
                            const float* __restrict__ coeffs) {
    int n = threadIdx.x;                       // 512 threads
    float s = 0.f;
    #pragma unroll 8
    for (int j = 0; j < HD; j++) s += W1[j * MEMH + n];
    g_b1eff[n] = b1[n] + coeffs[0] * s;
}

// ---------------------------------------------------------------------------
// GEMM1: q = clip(hs @ Wq, +-10) -> g_qs.   128x128 block tile, BK=16,
// 256 threads, 8x8 per-thread tile, FFMA2 pairs along the n dimension.
// ---------------------------------------------------------------------------
__global__ __launch_bounds__(256) void qproj_kernel(const float* __restrict__ hs,
                                                    const float* __restrict__ Wq) {
    __shared__ __align__(16) float As[16][128];   // transposed: As[k][m]
    __shared__ __align__(16) float Bs[16][128];   // Bs[k][n]
    const int tid = threadIdx.x;
    const int m0 = blockIdx.y * 128;
    const int n0 = blockIdx.x * 128;
    const int tx = tid & 15;     // n-group (8 cols)
    const int ty = tid >> 4;     // m-group (8 rows)

    u64 acc[8][4];
    #pragma unroll
    for (int i = 0; i < 8; i++)
        #pragma unroll
        for (int j = 0; j < 4; j++) acc[i][j] = 0ull;   // (+0.f, +0.f)

    for (int k0 = 0; k0 < HIDDEN; k0 += 16) {
        #pragma unroll
        for (int i = 0; i < 2; i++) {
            int l = tid + i * 256;
            int m = l >> 2, kq = (l & 3) * 4;
            float4 v = *(const float4*)&hs[(size_t)(m0 + m) * HIDDEN + k0 + kq];
            As[kq + 0][m] = v.x; As[kq + 1][m] = v.y;
            As[kq + 2][m] = v.z; As[kq + 3][m] = v.w;
        }
        #pragma unroll
        for (int i = 0; i < 2; i++) {
            int l = tid + i * 256;
            int kr = l >> 5, nq = (l & 31) * 4;
            *(float4*)&Bs[kr][nq] =
                *(const float4*)&Wq[(size_t)(k0 + kr) * HIDDEN + n0 + nq];
        }
        __syncthreads();
        #pragma unroll
        for (int kk = 0; kk < 16; kk++) {
            float4 a0 = *(const float4*)&As[kk][ty * 8];
            float4 a1 = *(const float4*)&As[kk][ty * 8 + 4];
            const u64* bp = (const u64*)&Bs[kk][tx * 8];
            u64 b0 = bp[0], b1v = bp[1], b2v = bp[2], b3v = bp[3];
            float ar[8] = {a0.x, a0.y, a0.z, a0.w, a1.x, a1.y, a1.z, a1.w};
            #pragma unroll
            for (int i = 0; i < 8; i++) {
                u64 ap = pack2(ar[i], ar[i]);
                ffma2(acc[i][0], ap, b0);
                ffma2(acc[i][1], ap, b1v);
                ffma2(acc[i][2], ap, b2v);
                ffma2(acc[i][3], ap, b3v);
            }
        }
        __syncthreads();
    }

    #pragma unroll
    for (int i = 0; i < 8; i++) {
        size_t base = (size_t)(m0 + ty * 8 + i) * HIDDEN + n0 + tx * 8;
        float o[8];
        #pragma unroll
        for (int jp = 0; jp < 4; jp++) {
            float2 v = unpack2(acc[i][jp]);
            o[jp * 2]     = fminf(fmaxf(v.x, -10.f), 10.f);
            o[jp * 2 + 1] = fminf(fmaxf(v.y, -10.f), 10.f);
        }
        *(float4*)&g_qs[base]     = make_float4(o[0], o[1], o[2], o[3]);
        *(float4*)&g_qs[base + 4] = make_float4(o[4], o[5], o[6], o[7]);
    }
}

// ---------------------------------------------------------------------------
// Fused MLP: per block, 64 flat rows.
//   Pt[k][r] : transposed poly features (row-pairs contiguous -> free FFMA2 packs)
//   GEMM2: h = relu(P @ W1[64:,:] + b1eff), in 4 chunks of 128 cols
//   Ht[k][r]: transposed h chunk
//   GEMM3: out += Ht-chunk^T @ W2[:, :64], accumulated in registers; + b2[:64]
// Thread map: tx = tid&31, ty = tid>>5 (warp == fixed ty -> all smem A-side
// loads are warp-broadcast, conflict-free; all LDGs fully coalesced).
// ---------------------------------------------------------------------------
__global__ __launch_bounds__(256) void mlp_kernel(const float* __restrict__ coeffs,
                                                  const float* __restrict__ W1,
                                                  const float* __restrict__ W2,
                                                  const float* __restrict__ b2,
                                                  float* __restrict__ out) {
    extern __shared__ float sm[];
    float* Pt = sm;                 // [KP][64]   = 48 KB
    float* Ht = sm + KP * 64;       // [128][68]  = 34 KB (also reused as staging)
    const int tid = threadIdx.x;
    const int tx = tid & 31;
    const int ty = tid >> 5;
    const int r0 = blockIdx.x * 64;

    const float c1 = coeffs[1], c2 = coeffs[2], c3 = coeffs[3];

    // ---- Build transposed poly tile (via staging buffer to avoid bank conflicts)
    const float* qb = g_qs + (size_t)r0 * HD;   // 64 rows x 64 dims, contiguous
    float* Xs = Ht;                              // staging [64][65]
    for (int l = tid; l < 64 * HD; l += 256) {   // coalesced LDG, conflict-free STS
        Xs[(l >> 6) * 65 + (l & 63)] = qb[l];
    }
    __syncthreads();
    for (int l = tid; l < 64 * HD; l += 256) {
        int d = l >> 6, r = l & 63;              // lanes: consecutive r
        float x = Xs[r * 65 + d];                // stride-65 -> conflict-free
        float x2 = x * x;
        float p1 = c1 * x;
        float p2 = c2 * x2;
        float p3 = c3 * x2 * x;
        p1 = fminf(fmaxf(p1, -1e6f), 1e6f);
        p2 = fminf(fmaxf(p2, -1e6f), 1e6f);
        p3 = fminf(fmaxf(p3, -1e6f), 1e6f);
        Pt[d * 64 + r]          = p1;            // conflict-free (r contiguous)
        Pt[(64 + d) * 64 + r]   = p2;
        Pt[(128 + d) * 64 + r]  = p3;
    }

    // ---- Output accumulators: 4 row-pairs x 2 cols, init with b2
    u64 acc3[4][2];
    {
        float2 b2v = *(const float2*)&b2[tx * 2];
        #pragma unroll
        for (int rp = 0; rp < 4; rp++) {
            acc3[rp][0] = pack2(b2v.x, b2v.x);
            acc3[rp][1] = pack2(b2v.y, b2v.y);
        }
    }
    __syncthreads();   // Pt ready; Xs (==Ht) reads done

    for (int nc = 0; nc < 4; nc++) {
        const int n0 = nc * 128;

        // ---- GEMM2 chunk: h[64][128] = relu(P @ W1eff + b1eff)
        u64 acc2[4][4];                          // [row-pair][col]
        {
            float4 bv = *(const float4*)&g_b1eff[n0 + tx * 4];
            float bb[4] = {bv.x, bv.y, bv.z, bv.w};
            #pragma unroll
            for (int rp = 0; rp < 4; rp++)
                #pragma unroll
                for (int j = 0; j < 4; j++) acc2[rp][j] = pack2(bb[j], bb[j]);
        }
        #pragma unroll 4
        for (int k = 0; k < KP; k++) {
            float4 w = *(const float4*)&W1[(size_t)(HD + k) * MEMH + n0 + tx * 4];
            u64 wp0 = pack2(w.x, w.x), wp1 = pack2(w.y, w.y);
            u64 wp2 = pack2(w.z, w.z), wp3 = pack2(w.w, w.w);
            ulonglong2 aA = *(const ulonglong2*)&Pt[k * 64 + ty * 8];       // broadcast
            ulonglong2 aB = *(const ulonglong2*)&Pt[k * 64 + ty * 8 + 4];
            u64 ap[4] = {aA.x, aA.y, aB.x, aB.y};
            #pragma unroll
            for (int rp = 0; rp < 4; rp++) {
                ffma2(acc2[rp][0], ap[rp], wp0);
                ffma2(acc2[rp][1], ap[rp], wp1);
                ffma2(acc2[rp][2], ap[rp], wp2);
                ffma2(acc2[rp][3], ap[rp], wp3);
            }
        }

        if (nc) __syncthreads();                 // prior GEMM3 reads of Ht done

        // ---- ReLU + store transposed h chunk
        #pragma unroll
        for (int rp = 0; rp < 4; rp++)
            #pragma unroll
            for (int j = 0; j < 4; j++) {
                float2 v = unpack2(acc2[rp][j]);
                v.x = fmaxf(v.x, 0.f);
                v.y = fmaxf(v.y, 0.f);
                *(u64*)&Ht[(tx * 4 + j) * HT_STRIDE + ty * 8 + rp * 2] = pack2(v.x, v.y);
            }
        __syncthreads();

        // ---- GEMM3 chunk: acc3 += Ht^T @ W2[n0:n0+128, 0:64]
        #pragma unroll 4
        for (int k = 0; k < 128; k++) {
            float2 wv = *(const float2*)&W2[(size_t)(n0 + k) * 256 + tx * 2];
            u64 wq0 = pack2(wv.x, wv.x);
            u64 wq1 = pack2(wv.y, wv.y);
            ulonglong2 hA = *(const ulonglong2*)&Ht[k * HT_STRIDE + ty * 8];     // broadcast
            ulonglong2 hB = *(const ulonglong2*)&Ht[k * HT_STRIDE + ty * 8 + 4];
            u64 hp[4] = {hA.x, hA.y, hB.x, hB.y};
            #pragma unroll
            for (int rp = 0; rp < 4; rp++) {
                ffma2(acc3[rp][0], hp[rp], wq0);
                ffma2(acc3[rp][1], hp[rp], wq1);
            }
        }
    }

    // ---- Store: rows (r0 + ty*8 + rp*2 [+1]), cols tx*2 + cj
    #pragma unroll
    for (int rp = 0; rp < 4; rp++) {
        int r = r0 + ty * 8 + rp * 2;
        #pragma unroll
        for (int cj = 0; cj < 2; cj++) {
            float2 v = unpack2(acc3[rp][cj]);
            out[(size_t)r       * HD + tx * 2 + cj] = v.x;
            out[(size_t)(r + 1) * HD + tx * 2 + cj] = v.y;
        }
    }
}

// ---------------------------------------------------------------------------
extern "C" void kernel_launch(void* const* d_in, const int* in_sizes, int n_in,
                              void* d_out, int out_size) {
    const float* hs     = (const float*)d_in[0];
    const float* Wq     = (const float*)d_in[1];
    const float* coeffs = (const float*)d_in[2];
    const float* W1     = (const float*)d_in[3];
    const float* b1     = (const float*)d_in[4];
    const float* W2     = (const float*)d_in[5];
    const float* b2     = (const float*)d_in[6];
    float* out = (float*)d_out;

    prep_kernel<<<1, MEMH>>>(W1, b1, coeffs);

    dim3 g1(HIDDEN / 128, TOKENS / 128);
    qproj_kernel<<<g1, 256>>>(hs, Wq);

    const int smem2 = (KP * 64 + 128 * HT_STRIDE) * (int)sizeof(float);  // 83968 B
    cudaFuncSetAttribute(mlp_kernel, cudaFuncAttributeMaxDynamicSharedMemorySize, smem2);
    mlp_kernel<<<FLATR / 64, 256, smem2>>>(coeffs, W1, W2, b2, out);
}

// round 3
// speedup vs baseline: 2.2003x; 2.2003x over previous
#include <cuda_runtime.h>
#include <cuda_bf16.h>

// ---------------------------------------------------------------------------
// AtlasAttention, all-tensor via legacy mma.sync (bf16, split-3 precision).
// tcgen05 is unavailable: harness compiles PTX for plain sm_103 (no 'a').
// Pipeline:
//   prep:  split hs, Wq^T, W1eff^T, W2^T into bf16 hi/lo; fold const poly
//          block into b1eff.
//   GEMM1: q = clip(hs@Wq); epilogue computes poly features -> P hi/lo
//   GEMM2: h = relu(P@W1eff + b1eff) -> H hi/lo
//   GEMM3: out = H@W2[:, :64] + b2
// Each GEMM: C = Ah*Bh + Ah*Bl + Al*Bh  (fp32 accum), m16n8k16 bf16 mma.
// ---------------------------------------------------------------------------

typedef unsigned int u32;

#define TOKENS 8192
#define HIDDEN 768
#define FLATR  98304
#define MEMH   512
#define KP     192
#define HD     64

__device__ __align__(16) __nv_bfloat16 g_hs_hi[TOKENS * HIDDEN];
__device__ __align__(16) __nv_bfloat16 g_hs_lo[TOKENS * HIDDEN];
__device__ __align__(16) __nv_bfloat16 g_wqt_hi[HIDDEN * HIDDEN];  // [n][k]
__device__ __align__(16) __nv_bfloat16 g_wqt_lo[HIDDEN * HIDDEN];
__device__ __align__(16) __nv_bfloat16 g_P_hi[(size_t)FLATR * KP];  // [flat][192]
__device__ __align__(16) __nv_bfloat16 g_P_lo[(size_t)FLATR * KP];
__device__ __align__(16) __nv_bfloat16 g_H_hi[(size_t)FLATR * MEMH];
__device__ __align__(16) __nv_bfloat16 g_H_lo[(size_t)FLATR * MEMH];
__device__ __align__(16) __nv_bfloat16 g_w1t_hi[MEMH * KP];         // [n=512][k=192]
__device__ __align__(16) __nv_bfloat16 g_w1t_lo[MEMH * KP];
__device__ __align__(16) __nv_bfloat16 g_w2t_hi[HD * MEMH];         // [n=64][k=512]
__device__ __align__(16) __nv_bfloat16 g_w2t_lo[HD * MEMH];
__device__ float g_b1eff[MEMH];

// ---------------- helpers ----------------
__device__ __forceinline__ u32 smem_u32(const void* p) {
    u32 a; asm("{ .reg .u64 t; cvta.to.shared.u64 t, %1; cvt.u32.u64 %0, t; }"
               : "=r"(a) : "l"(p)); return a;
}
__device__ __forceinline__ u32 pack_bf(__nv_bfloat16 a, __nv_bfloat16 b) {
    return (u32)__bfloat16_as_ushort(a) | ((u32)__bfloat16_as_ushort(b) << 16);
}
__device__ __forceinline__ void split2(float v0, float v1, u32 &hi, u32 &lo) {
    __nv_bfloat16 h0 = __float2bfloat16(v0), h1 = __float2bfloat16(v1);
    __nv_bfloat16 l0 = __float2bfloat16(v0 - __bfloat162float(h0));
    __nv_bfloat16 l1 = __float2bfloat16(v1 - __bfloat162float(h1));
    hi = pack_bf(h0, h1); lo = pack_bf(l0, l1);
}
__device__ __forceinline__ void mma16816(float* c, const u32* a, const u32* b) {
    asm volatile(
        "mma.sync.aligned.m16n8k16.row.col.f32.bf16.bf16.f32 "
        "{%0,%1,%2,%3}, {%4,%5,%6,%7}, {%8,%9}, {%0,%1,%2,%3};"
        : "+f"(c[0]), "+f"(c[1]), "+f"(c[2]), "+f"(c[3])
        : "r"(a[0]), "r"(a[1]), "r"(a[2]), "r"(a[3]), "r"(b[0]), "r"(b[1]));
}
__device__ __forceinline__ void cpasync16(u32 dst, const void* src) {
    asm volatile("cp.async.cg.shared.global [%0], [%1], 16;" :: "r"(dst), "l"(src));
}

// ---------------- prep kernels ----------------
__global__ void prep_b1eff(const float* __restrict__ W1, const float* __restrict__ b1,
                           const float* __restrict__ coeffs) {
    int n = threadIdx.x;
    float s = 0.f;
    #pragma unroll 8
    for (int j = 0; j < HD; j++) s += W1[j * MEMH + n];
    g_b1eff[n] = b1[n] + coeffs[0] * s;
}
__global__ void split_hs(const float* __restrict__ hs) {
    int i4 = blockIdx.x * 256 + threadIdx.x;        // per 4 elements
    float4 v = ((const float4*)hs)[i4];
    u32 h0, l0, h1, l1;
    split2(v.x, v.y, h0, l0);
    split2(v.z, v.w, h1, l1);
    ((u32*)g_hs_hi)[i4 * 2] = h0; ((u32*)g_hs_hi)[i4 * 2 + 1] = h1;
    ((u32*)g_hs_lo)[i4 * 2] = l0; ((u32*)g_hs_lo)[i4 * 2 + 1] = l1;
}
__global__ void split_wqt(const float* __restrict__ Wq) {
    int idx = blockIdx.x * 256 + threadIdx.x;       // n*768+k
    int n = idx / HIDDEN, k = idx - n * HIDDEN;
    float v = Wq[(size_t)k * HIDDEN + n];
    __nv_bfloat16 hi = __float2bfloat16(v);
    g_wqt_hi[idx] = hi;
    g_wqt_lo[idx] = __float2bfloat16(v - __bfloat162float(hi));
}
__global__ void split_w1t(const float* __restrict__ W1) {
    int idx = blockIdx.x * 256 + threadIdx.x;       // n*192+k
    int n = idx / KP, k = idx - n * KP;
    float v = W1[(size_t)(HD + k) * MEMH + n];
    __nv_bfloat16 hi = __float2bfloat16(v);
    g_w1t_hi[idx] = hi;
    g_w1t_lo[idx] = __float2bfloat16(v - __bfloat162float(hi));
}
__global__ void split_w2t(const float* __restrict__ W2) {
    int idx = blockIdx.x * 256 + threadIdx.x;       // n*512+k
    int n = idx >> 9, k = idx & 511;
    float v = W2[(size_t)k * 256 + n];
    __nv_bfloat16 hi = __float2bfloat16(v);
    g_w2t_hi[idx] = hi;
    g_w2t_lo[idx] = __float2bfloat16(v - __bfloat162float(hi));
}

// ---------------- unified split-3 GEMM ----------------
// A [M][K] row-major (hi/lo), B [N][K] k-major (hi/lo), C 128 x BN per block.
// 8 warps: warpM = wid&3 (32 rows), warpN = wid>>2 (NT*8 cols).
template <int BN, int NT, int MODE>
__global__ __launch_bounds__(256) void gemm_split3(const float* __restrict__ coeffs,
                                                   const float* __restrict__ b2,
                                                   float* __restrict__ outf) {
    constexpr int BM = 128, BK = 32;
    constexpr int SA = 20;                 // u32 row stride (16 data + 4 pad)
    constexpr int TILE_A = BM * SA;
    constexpr int TILE_B = BN * SA;
    constexpr int STAGE = 2 * TILE_A + 2 * TILE_B;
    constexpr int K   = (MODE == 1) ? HIDDEN : (MODE == 2) ? KP : MEMH;
    constexpr int NIT = K / BK;

    const __nv_bfloat16 *Ahi, *Alo, *Bhi, *Blo;
    if (MODE == 1) { Ahi = g_hs_hi; Alo = g_hs_lo; Bhi = g_wqt_hi; Blo = g_wqt_lo; }
    else if (MODE == 2) { Ahi = g_P_hi; Alo = g_P_lo; Bhi = g_w1t_hi; Blo = g_w1t_lo; }
    else { Ahi = g_H_hi; Alo = g_H_lo; Bhi = g_w2t_hi; Blo = g_w2t_lo; }

    extern __shared__ u32 smem[];
    const u32 sbase = smem_u32(smem);

    const int tid = threadIdx.x, wid = tid >> 5, lane = tid & 31;
    const int g = lane >> 2, tg = lane & 3;
    const int m0 = blockIdx.x * BM, n0 = blockIdx.y * BN;
    const int warpM = wid & 3, warpN = wid >> 2;

    float acc[2][NT][4];
    #pragma unroll
    for (int mt = 0; mt < 2; mt++)
        #pragma unroll
        for (int nt = 0; nt < NT; nt++)
            #pragma unroll
            for (int j = 0; j < 4; j++) acc[mt][nt][j] = 0.f;

    auto load_stage = [&](int s, int k0) {
        const u32 stb = sbase + (u32)s * STAGE * 4;
        #pragma unroll
        for (int t = 0; t < 2; t++) {
            const __nv_bfloat16* src = t ? Alo : Ahi;
            #pragma unroll
            for (int idx = 0; idx < 2; idx++) {
                int l = tid + idx * 256;            // BM*4 = 512 chunks
                int r = l >> 2, c = l & 3;
                cpasync16(stb + (u32)(t * TILE_A + r * SA) * 4 + c * 16,
                          src + (size_t)(m0 + r) * K + k0 + c * 8);
            }
        }
        #pragma unroll
        for (int t = 0; t < 2; t++) {
            const __nv_bfloat16* src = t ? Blo : Bhi;
            #pragma unroll
            for (int idx = 0; idx < (BN * 4 + 255) / 256; idx++) {
                int l = tid + idx * 256;
                if (BN * 4 % 256 == 0 || l < BN * 4) {
                    int r = l >> 2, c = l & 3;
                    cpasync16(stb + (u32)(2 * TILE_A + t * TILE_B + r * SA) * 4 + c * 16,
                              src + (size_t)(n0 + r) * K + k0 + c * 8);
                }
            }
        }
        asm volatile("cp.async.commit_group;");
    };

    load_stage(0, 0);
    for (int it = 0; it < NIT; it++) {
        if (it + 1 < NIT) {
            load_stage((it + 1) & 1, (it + 1) * BK);
            asm volatile("cp.async.wait_group %0;" :: "n"(1));
        } else {
            asm volatile("cp.async.wait_group %0;" :: "n"(0));
        }
        __syncthreads();
        const u32* S = smem + (it & 1) * STAGE;
        #pragma unroll
        for (int kt = 0; kt < 2; kt++) {
            u32 ah[2][4], al[2][4];
            #pragma unroll
            for (int mt = 0; mt < 2; mt++) {
                int off = (warpM * 32 + mt * 16 + g) * SA + kt * 8 + tg;
                ah[mt][0] = S[off];          ah[mt][1] = S[off + 8 * SA];
                ah[mt][2] = S[off + 4];      ah[mt][3] = S[off + 8 * SA + 4];
                const u32* SL = S + TILE_A;
                al[mt][0] = SL[off];         al[mt][1] = SL[off + 8 * SA];
                al[mt][2] = SL[off + 4];     al[mt][3] = SL[off + 8 * SA + 4];
            }
            u32 bh[NT][2], bl[NT][2];
            #pragma unroll
            for (int nt = 0; nt < NT; nt++) {
                int off = (warpN * NT * 8 + nt * 8 + g) * SA + kt * 8 + tg;
                const u32* SBh = S + 2 * TILE_A;
                const u32* SBl = S + 2 * TILE_A + TILE_B;
                bh[nt][0] = SBh[off]; bh[nt][1] = SBh[off + 4];
                bl[nt][0] = SBl[off]; bl[nt][1] = SBl[off + 4];
            }
            #pragma unroll
            for (int mt = 0; mt < 2; mt++)
                #pragma unroll
                for (int nt = 0; nt < NT; nt++) mma16816(acc[mt][nt], ah[mt], bh[nt]);
            #pragma unroll
            for (int mt = 0; mt < 2; mt++)
                #pragma unroll
                for (int nt = 0; nt < NT; nt++) mma16816(acc[mt][nt], ah[mt], bl[nt]);
            #pragma unroll
            for (int mt = 0; mt < 2; mt++)
                #pragma unroll
                for (int nt = 0; nt < NT; nt++) mma16816(acc[mt][nt], al[mt], bh[nt]);
        }
        __syncthreads();
    }

    // ---- epilogue
    float c1v = 0.f, c2v = 0.f, c3v = 0.f;
    if (MODE == 1) { c1v = coeffs[1]; c2v = coeffs[2]; c3v = coeffs[3]; }
    #pragma unroll
    for (int mt = 0; mt < 2; mt++)
        #pragma unroll
        for (int nt = 0; nt < NT; nt++)
            #pragma unroll
            for (int h = 0; h < 2; h++) {
                int row = m0 + warpM * 32 + mt * 16 + g + h * 8;
                int col = n0 + warpN * NT * 8 + nt * 8 + tg * 2;
                float v0 = acc[mt][nt][h * 2], v1 = acc[mt][nt][h * 2 + 1];
                if (MODE == 1) {
                    float x0 = fminf(fmaxf(v0, -10.f), 10.f);
                    float x1 = fminf(fmaxf(v1, -10.f), 10.f);
                    int head = col >> 6, d = col & 63;
                    size_t base = ((size_t)row * 12 + head) * 96 + (d >> 1);
                    float p0[3] = {c1v * x0, c2v * x0 * x0, c3v * x0 * x0 * x0};
                    float p1[3] = {c1v * x1, c2v * x1 * x1, c3v * x1 * x1 * x1};
                    #pragma unroll
                    for (int fi = 0; fi < 3; fi++) {
                        float a = fminf(fmaxf(p0[fi], -1e6f), 1e6f);
                        float b = fminf(fmaxf(p1[fi], -1e6f), 1e6f);
                        u32 hi, lo; split2(a, b, hi, lo);
                        ((u32*)g_P_hi)[base + fi * 32] = hi;
                        ((u32*)g_P_lo)[base + fi * 32] = lo;
                    }
                } else if (MODE == 2) {
                    v0 = fmaxf(v0 + g_b1eff[col], 0.f);
                    v1 = fmaxf(v1 + g_b1eff[col + 1], 0.f);
                    u32 hi, lo; split2(v0, v1, hi, lo);
                    size_t base = (size_t)row * 256 + (col >> 1);
                    ((u32*)g_H_hi)[base] = hi;
                    ((u32*)g_H_lo)[base] = lo;
                } else {
                    float2 o = make_float2(v0 + b2[col], v1 + b2[col + 1]);
                    *(float2*)&outf[(size_t)row * HD + col] = o;
                }
            }
}

// ---------------------------------------------------------------------------
extern "C" void kernel_launch(void* const* d_in, const int* in_sizes, int n_in,
                              void* d_out, int out_size) {
    const float* hs     = (const float*)d_in[0];
    const float* Wq     = (const float*)d_in[1];
    const float* coeffs = (const float*)d_in[2];
    const float* W1     = (const float*)d_in[3];
    const float* b1     = (const float*)d_in[4];
    const float* W2     = (const float*)d_in[5];
    const float* b2     = (const float*)d_in[6];
    float* out = (float*)d_out;

    prep_b1eff<<<1, MEMH>>>(W1, b1, coeffs);
    split_hs<<<(TOKENS * HIDDEN / 4) / 256, 256>>>(hs);
    split_wqt<<<(HIDDEN * HIDDEN) / 256, 256>>>(Wq);
    split_w1t<<<(MEMH * KP) / 256, 256>>>(W1);
    split_w2t<<<(HD * MEMH) / 256, 256>>>(W2);

    constexpr int SM128 = (2 * 128 * 20 + 2 * 128 * 20) * 4 * 2;   // 81920 B
    constexpr int SM64  = (2 * 128 * 20 + 2 * 64 * 20) * 4 * 2;    // 61440 B
    cudaFuncSetAttribute((const void*)gemm_split3<128, 8, 1>,
                         cudaFuncAttributeMaxDynamicSharedMemorySize, SM128);
    cudaFuncSetAttribute((const void*)gemm_split3<128, 8, 2>,
                         cudaFuncAttributeMaxDynamicSharedMemorySize, SM128);
    cudaFuncSetAttribute((const void*)gemm_split3<64, 4, 3>,
                         cudaFuncAttributeMaxDynamicSharedMemorySize, SM64);

    gemm_split3<128, 8, 1><<<dim3(TOKENS / 128, HIDDEN / 128), 256, SM128>>>(coeffs, b2, out);
    gemm_split3<128, 8, 2><<<dim3(FLATR / 128, MEMH / 128), 256, SM128>>>(coeffs, b2, out);
    gemm_split3<64, 4, 3><<<dim3(FLATR / 128, 1), 256, SM64>>>(coeffs, b2, out);
}

// round 4
// speedup vs baseline: 2.5782x; 1.1717x over previous
#include <cuda_runtime.h>
#include <cuda_bf16.h>

// ---------------------------------------------------------------------------
// AtlasAttention, legacy mma.sync bf16 split-3, fused MLP.
//   GEMM1: q = clip(hs@Wq) -> g_qs (fp32), split-3 HMMA
//   Fused per 128 flat rows: poly(q)->P smem; 8 chunks of 64 cols:
//       GEMM2 (P x W1chunk) -> relu+split -> H smem -> GEMM3 accum in regs
//   out = acc + b2.  Exact folds: b1eff (const poly block), W2[:, :64] slice.
// ---------------------------------------------------------------------------

typedef unsigned int u32;

#define TOKENS 8192
#define HIDDEN 768
#define FLATR  98304
#define MEMH   512
#define KP     192
#define HD     64

__device__ __align__(16) __nv_bfloat16 g_hs_hi[TOKENS * HIDDEN];
__device__ __align__(16) __nv_bfloat16 g_hs_lo[TOKENS * HIDDEN];
__device__ __align__(16) __nv_bfloat16 g_wqt_hi[HIDDEN * HIDDEN];  // [n][k]
__device__ __align__(16) __nv_bfloat16 g_wqt_lo[HIDDEN * HIDDEN];
__device__ __align__(16) __nv_bfloat16 g_w1t_hi[MEMH * KP];        // [n=512][k=192]
__device__ __align__(16) __nv_bfloat16 g_w1t_lo[MEMH * KP];
__device__ __align__(16) __nv_bfloat16 g_w2t_hi[HD * MEMH];        // [n=64][k=512]
__device__ __align__(16) __nv_bfloat16 g_w2t_lo[HD * MEMH];
__device__ float g_qs[(size_t)FLATR * HD];                         // clipped q
__device__ float g_b1eff[MEMH];

// ---------------- helpers ----------------
__device__ __forceinline__ u32 smem_u32(const void* p) {
    u32 a; asm("{ .reg .u64 t; cvta.to.shared.u64 t, %1; cvt.u32.u64 %0, t; }"
               : "=r"(a) : "l"(p)); return a;
}
__device__ __forceinline__ u32 pack_bf(__nv_bfloat16 a, __nv_bfloat16 b) {
    return (u32)__bfloat16_as_ushort(a) | ((u32)__bfloat16_as_ushort(b) << 16);
}
__device__ __forceinline__ void split2(float v0, float v1, u32 &hi, u32 &lo) {
    __nv_bfloat16 h0 = __float2bfloat16(v0), h1 = __float2bfloat16(v1);
    __nv_bfloat16 l0 = __float2bfloat16(v0 - __bfloat162float(h0));
    __nv_bfloat16 l1 = __float2bfloat16(v1 - __bfloat162float(h1));
    hi = pack_bf(h0, h1); lo = pack_bf(l0, l1);
}
__device__ __forceinline__ void mma16816(float* c, const u32* a, const u32* b) {
    asm volatile(
        "mma.sync.aligned.m16n8k16.row.col.f32.bf16.bf16.f32 "
        "{%0,%1,%2,%3}, {%4,%5,%6,%7}, {%8,%9}, {%0,%1,%2,%3};"
        : "+f"(c[0]), "+f"(c[1]), "+f"(c[2]), "+f"(c[3])
        : "r"(a[0]), "r"(a[1]), "r"(a[2]), "r"(a[3]), "r"(b[0]), "r"(b[1]));
}
__device__ __forceinline__ void cpasync16(u32 dst, const void* src) {
    asm volatile("cp.async.cg.shared.global [%0], [%1], 16;" :: "r"(dst), "l"(src));
}

// ---------------- prep kernels ----------------
__global__ void prep_b1eff(const float* __restrict__ W1, const float* __restrict__ b1,
                           const float* __restrict__ coeffs) {
    int n = threadIdx.x;
    float s = 0.f;
    #pragma unroll 8
    for (int j = 0; j < HD; j++) s += W1[j * MEMH + n];
    g_b1eff[n] = b1[n] + coeffs[0] * s;
}
__global__ void split_hs(const float* __restrict__ hs) {
    int i4 = blockIdx.x * 256 + threadIdx.x;
    float4 v = ((const float4*)hs)[i4];
    u32 h0, l0, h1, l1;
    split2(v.x, v.y, h0, l0);
    split2(v.z, v.w, h1, l1);
    ((u32*)g_hs_hi)[i4 * 2] = h0; ((u32*)g_hs_hi)[i4 * 2 + 1] = h1;
    ((u32*)g_hs_lo)[i4 * 2] = l0; ((u32*)g_hs_lo)[i4 * 2 + 1] = l1;
}
__global__ void split_wqt(const float* __restrict__ Wq) {
    int idx = blockIdx.x * 256 + threadIdx.x;
    int n = idx / HIDDEN, k = idx - n * HIDDEN;
    float v = Wq[(size_t)k * HIDDEN + n];
    __nv_bfloat16 hi = __float2bfloat16(v);
    g_wqt_hi[idx] = hi;
    g_wqt_lo[idx] = __float2bfloat16(v - __bfloat162float(hi));
}
__global__ void split_w1t(const float* __restrict__ W1) {
    int idx = blockIdx.x * 256 + threadIdx.x;
    int n = idx / KP, k = idx - n * KP;
    float v = W1[(size_t)(HD + k) * MEMH + n];
    __nv_bfloat16 hi = __float2bfloat16(v);
    g_w1t_hi[idx] = hi;
    g_w1t_lo[idx] = __float2bfloat16(v - __bfloat162float(hi));
}
__global__ void split_w2t(const float* __restrict__ W2) {
    int idx = blockIdx.x * 256 + threadIdx.x;
    int n = idx >> 9, k = idx & 511;
    float v = W2[(size_t)k * 256 + n];
    __nv_bfloat16 hi = __float2bfloat16(v);
    g_w2t_hi[idx] = hi;
    g_w2t_lo[idx] = __float2bfloat16(v - __bfloat162float(hi));
}

// ---------------- GEMM1: q = clip(hs@Wq), split-3 (R3 structure) ------------
__global__ __launch_bounds__(256) void gemm1_kernel() {
    constexpr int BM = 128, BN = 128, BK = 32, NT = 8;
    constexpr int SA = 20;
    constexpr int TILE_A = BM * SA, TILE_B = BN * SA;
    constexpr int STAGE = 2 * TILE_A + 2 * TILE_B;
    constexpr int K = HIDDEN, NIT = K / BK;

    extern __shared__ u32 smem[];
    const u32 sbase = smem_u32(smem);
    const int tid = threadIdx.x, wid = tid >> 5, lane = tid & 31;
    const int g = lane >> 2, tg = lane & 3;
    const int m0 = blockIdx.x * BM, n0 = blockIdx.y * BN;
    const int warpM = wid & 3, warpN = wid >> 2;

    float acc[2][NT][4];
    #pragma unroll
    for (int mt = 0; mt < 2; mt++)
        #pragma unroll
        for (int nt = 0; nt < NT; nt++)
            #pragma unroll
            for (int j = 0; j < 4; j++) acc[mt][nt][j] = 0.f;

    auto load_stage = [&](int s, int k0) {
        const u32 stb = sbase + (u32)s * STAGE * 4;
        #pragma unroll
        for (int t = 0; t < 2; t++) {
            const __nv_bfloat16* src = t ? g_hs_lo : g_hs_hi;
            #pragma unroll
            for (int idx = 0; idx < 2; idx++) {
                int l = tid + idx * 256;
                int r = l >> 2, c = l & 3;
                cpasync16(stb + (u32)(t * TILE_A + r * SA) * 4 + c * 16,
                          src + (size_t)(m0 + r) * K + k0 + c * 8);
            }
        }
        #pragma unroll
        for (int t = 0; t < 2; t++) {
            const __nv_bfloat16* src = t ? g_wqt_lo : g_wqt_hi;
            #pragma unroll
            for (int idx = 0; idx < 2; idx++) {
                int l = tid + idx * 256;
                int r = l >> 2, c = l & 3;
                cpasync16(stb + (u32)(2 * TILE_A + t * TILE_B + r * SA) * 4 + c * 16,
                          src + (size_t)(n0 + r) * K + k0 + c * 8);
            }
        }
        asm volatile("cp.async.commit_group;");
    };

    load_stage(0, 0);
    for (int it = 0; it < NIT; it++) {
        if (it + 1 < NIT) {
            load_stage((it + 1) & 1, (it + 1) * BK);
            asm volatile("cp.async.wait_group %0;" :: "n"(1));
        } else {
            asm volatile("cp.async.wait_group %0;" :: "n"(0));
        }
        __syncthreads();
        const u32* S = smem + (it & 1) * STAGE;
        #pragma unroll
        for (int kt = 0; kt < 2; kt++) {
            u32 ah[2][4], al[2][4];
            #pragma unroll
            for (int mt = 0; mt < 2; mt++) {
                int off = (warpM * 32 + mt * 16 + g) * SA + kt * 8 + tg;
                ah[mt][0] = S[off];       ah[mt][1] = S[off + 8 * SA];
                ah[mt][2] = S[off + 4];   ah[mt][3] = S[off + 8 * SA + 4];
                const u32* SL = S + TILE_A;
                al[mt][0] = SL[off];      al[mt][1] = SL[off + 8 * SA];
                al[mt][2] = SL[off + 4];  al[mt][3] = SL[off + 8 * SA + 4];
            }
            u32 bh[NT][2], bl[NT][2];
            #pragma unroll
            for (int nt = 0; nt < NT; nt++) {
                int off = (warpN * NT * 8 + nt * 8 + g) * SA + kt * 8 + tg;
                const u32* SBh = S + 2 * TILE_A;
                const u32* SBl = S + 2 * TILE_A + TILE_B;
                bh[nt][0] = SBh[off]; bh[nt][1] = SBh[off + 4];
                bl[nt][0] = SBl[off]; bl[nt][1] = SBl[off + 4];
            }
            #pragma unroll
            for (int mt = 0; mt < 2; mt++)
                #pragma unroll
                for (int nt = 0; nt < NT; nt++) mma16816(acc[mt][nt], ah[mt], bh[nt]);
            #pragma unroll
            for (int mt = 0; mt < 2; mt++)
                #pragma unroll
                for (int nt = 0; nt < NT; nt++) mma16816(acc[mt][nt], ah[mt], bl[nt]);
            #pragma unroll
            for (int mt = 0; mt < 2; mt++)
                #pragma unroll
                for (int nt = 0; nt < NT; nt++) mma16816(acc[mt][nt], al[mt], bh[nt]);
        }
        __syncthreads();
    }

    #pragma unroll
    for (int mt = 0; mt < 2; mt++)
        #pragma unroll
        for (int nt = 0; nt < NT; nt++)
            #pragma unroll
            for (int h = 0; h < 2; h++) {
                int row = m0 + warpM * 32 + mt * 16 + g + h * 8;
                int col = n0 + warpN * NT * 8 + nt * 8 + tg * 2;
                float v0 = fminf(fmaxf(acc[mt][nt][h * 2],     -10.f), 10.f);
                float v1 = fminf(fmaxf(acc[mt][nt][h * 2 + 1], -10.f), 10.f);
                *(float2*)&g_qs[(size_t)row * HIDDEN + col] = make_float2(v0, v1);
            }
}

// ---------------- fused MLP kernel ----------------
// smem (u32 units):
#define SP 100
#define SH 36
#define O_PHI   0                          // 128*100
#define O_PLO   12800
#define O_B2HI  25600                      // 64*100
#define O_B2LO  32000
#define O_HHI   38400                      // 128*36
#define O_HLO   43008
#define O_B3    47616                      // 2 parities x (hi 2304 + lo 2304)
#define SMEM_FUSED_U32 56832               // * 4 = 227328 B

__global__ __launch_bounds__(256) void mlp_fused(const float* __restrict__ coeffs,
                                                 const float* __restrict__ b2,
                                                 float* __restrict__ outf) {
    extern __shared__ u32 smem[];
    const u32 sbase = smem_u32(smem);
    const int tid = threadIdx.x, wid = tid >> 5, lane = tid & 31;
    const int g = lane >> 2, tg = lane & 3;
    const int r0 = blockIdx.x * 128;
    const int warpM = wid & 3, warpN = wid >> 2;   // warpN in {0,1}

    auto load_b2 = [&](int c) {
        #pragma unroll
        for (int t = 0; t < 2; t++) {
            const __nv_bfloat16* src = t ? g_w1t_lo : g_w1t_hi;
            u32 base = sbase + (t ? O_B2LO : O_B2HI) * 4;
            #pragma unroll
            for (int i = 0; i < 6; i++) {
                int l = tid + i * 256;                 // 64 rows * 24 chunks
                int n = l / 24, ch = l - n * 24;
                cpasync16(base + (u32)n * (SP * 4) + ch * 16,
                          src + (size_t)(c * 64 + n) * KP + ch * 8);
            }
        }
    };
    auto load_b3 = [&](int c, int par) {
        #pragma unroll
        for (int t = 0; t < 2; t++) {
            const __nv_bfloat16* src = t ? g_w2t_lo : g_w2t_hi;
            u32 base = sbase + (O_B3 + par * 4608 + t * 2304) * 4;
            #pragma unroll
            for (int i = 0; i < 2; i++) {
                int l = tid + i * 256;                 // 64 rows * 8 chunks
                int n = l >> 3, ch = l & 7;
                cpasync16(base + (u32)n * (SH * 4) + ch * 16,
                          src + (size_t)n * MEMH + c * 64 + ch * 8);
            }
        }
    };

    load_b2(0);
    load_b3(0, 0);
    asm volatile("cp.async.commit_group;");

    // ---- poly expansion: q -> P hi/lo in smem
    {
        const float c1 = coeffs[1], c2 = coeffs[2], c3 = coeffs[3];
        const float2* qb = (const float2*)(g_qs + (size_t)r0 * HD);
        #pragma unroll
        for (int i = 0; i < 16; i++) {
            int l = tid + i * 256;                     // 128 rows * 32 pairs
            int r = l >> 5, d2 = l & 31;
            float2 x = qb[l];
            float xa2 = x.x * x.x, xb2 = x.y * x.y;
            float pa[3] = {c1 * x.x, c2 * xa2, c3 * xa2 * x.x};
            float pb[3] = {c1 * x.y, c2 * xb2, c3 * xb2 * x.y};
            #pragma unroll
            for (int fi = 0; fi < 3; fi++) {
                float a = fminf(fmaxf(pa[fi], -1e6f), 1e6f);
                float b = fminf(fmaxf(pb[fi], -1e6f), 1e6f);
                u32 hi, lo; split2(a, b, hi, lo);
                smem[O_PHI + r * SP + fi * 32 + d2] = hi;
                smem[O_PLO + r * SP + fi * 32 + d2] = lo;
            }
        }
    }
    asm volatile("cp.async.wait_group %0;" :: "n"(0));
    __syncthreads();

    float acc3[2][4][4];
    #pragma unroll
    for (int mt = 0; mt < 2; mt++)
        #pragma unroll
        for (int nt = 0; nt < 4; nt++)
            #pragma unroll
            for (int j = 0; j < 4; j++) acc3[mt][nt][j] = 0.f;

    for (int c = 0; c < 8; c++) {
        // ---- GEMM2: [128 x 64] = P[128 x 192] * B2^T, split-3
        float acc2[2][4][4];
        #pragma unroll
        for (int mt = 0; mt < 2; mt++)
            #pragma unroll
            for (int nt = 0; nt < 4; nt++)
                #pragma unroll
                for (int j = 0; j < 4; j++) acc2[mt][nt][j] = 0.f;

        #pragma unroll
        for (int kt = 0; kt < 12; kt++) {
            u32 ah[2][4], al[2][4];
            #pragma unroll
            for (int mt = 0; mt < 2; mt++) {
                int off = (warpM * 32 + mt * 16 + g) * SP + kt * 8 + tg;
                ah[mt][0] = smem[O_PHI + off];          ah[mt][1] = smem[O_PHI + off + 8 * SP];
                ah[mt][2] = smem[O_PHI + off + 4];      ah[mt][3] = smem[O_PHI + off + 8 * SP + 4];
                al[mt][0] = smem[O_PLO + off];          al[mt][1] = smem[O_PLO + off + 8 * SP];
                al[mt][2] = smem[O_PLO + off + 4];      al[mt][3] = smem[O_PLO + off + 8 * SP + 4];
            }
            u32 bh[4][2], bl[4][2];
            #pragma unroll
            for (int nt = 0; nt < 4; nt++) {
                int off = (warpN * 32 + nt * 8 + g) * SP + kt * 8 + tg;
                bh[nt][0] = smem[O_B2HI + off]; bh[nt][1] = smem[O_B2HI + off + 4];
                bl[nt][0] = smem[O_B2LO + off]; bl[nt][1] = smem[O_B2LO + off + 4];
            }
            #pragma unroll
            for (int mt = 0; mt < 2; mt++)
                #pragma unroll
                for (int nt = 0; nt < 4; nt++) mma16816(acc2[mt][nt], ah[mt], bh[nt]);
            #pragma unroll
            for (int mt = 0; mt < 2; mt++)
                #pragma unroll
                for (int nt = 0; nt < 4; nt++) mma16816(acc2[mt][nt], ah[mt], bl[nt]);
            #pragma unroll
            for (int mt = 0; mt < 2; mt++)
                #pragma unroll
                for (int nt = 0; nt < 4; nt++) mma16816(acc2[mt][nt], al[mt], bh[nt]);
        }
        __syncthreads();                     // B2 consumed; H(c-1) consumed earlier

        // ---- relu + split -> H smem
        #pragma unroll
        for (int mt = 0; mt < 2; mt++)
            #pragma unroll
            for (int nt = 0; nt < 4; nt++) {
                int colg = c * 64 + warpN * 32 + nt * 8 + tg * 2;
                float2 bb = *(const float2*)&g_b1eff[colg];
                #pragma unroll
                for (int h = 0; h < 2; h++) {
                    int row = warpM * 32 + mt * 16 + g + h * 8;
                    int cu  = warpN * 16 + nt * 4 + tg;
                    float v0 = fmaxf(acc2[mt][nt][h * 2]     + bb.x, 0.f);
                    float v1 = fmaxf(acc2[mt][nt][h * 2 + 1] + bb.y, 0.f);
                    u32 hi, lo; split2(v0, v1, hi, lo);
                    smem[O_HHI + row * SH + cu] = hi;
                    smem[O_HLO + row * SH + cu] = lo;
                }
            }
        if (c < 7) {
            load_b2(c + 1);
            load_b3(c + 1, (c + 1) & 1);
            asm volatile("cp.async.commit_group;");
        }
        __syncthreads();                     // H visible

        // ---- GEMM3 accumulate: acc3 += H[128 x 64] * B3^T (overlaps cp.async)
        const int b3h = O_B3 + (c & 1) * 4608;
        const int b3l = b3h + 2304;
        #pragma unroll
        for (int kt = 0; kt < 4; kt++) {
            u32 ah[2][4], al[2][4];
            #pragma unroll
            for (int mt = 0; mt < 2; mt++) {
                int off = (warpM * 32 + mt * 16 + g) * SH + kt * 8 + tg;
                ah[mt][0] = smem[O_HHI + off];          ah[mt][1] = smem[O_HHI + off + 8 * SH];
                ah[mt][2] = smem[O_HHI + off + 4];      ah[mt][3] = smem[O_HHI + off + 8 * SH + 4];
                al[mt][0] = smem[O_HLO + off];          al[mt][1] = smem[O_HLO + off + 8 * SH];
                al[mt][2] = smem[O_HLO + off + 4];      al[mt][3] = smem[O_HLO + off + 8 * SH + 4];
            }
            u32 bh[4][2], bl[4][2];
            #pragma unroll
            for (int nt = 0; nt < 4; nt++) {
                int off = (warpN * 32 + nt * 8 + g) * SH + kt * 8 + tg;
                bh[nt][0] = smem[b3h + off]; bh[nt][1] = smem[b3h + off + 4];
                bl[nt][0] = smem[b3l + off]; bl[nt][1] = smem[b3l + off + 4];
            }
            #pragma unroll
            for (int mt = 0; mt < 2; mt++)
                #pragma unroll
                for (int nt = 0; nt < 4; nt++) mma16816(acc3[mt][nt], ah[mt], bh[nt]);
            #pragma unroll
            for (int mt = 0; mt < 2; mt++)
                #pragma unroll
                for (int nt = 0; nt < 4; nt++) mma16816(acc3[mt][nt], ah[mt], bl[nt]);
            #pragma unroll
            for (int mt = 0; mt < 2; mt++)
                #pragma unroll
                for (int nt = 0; nt < 4; nt++) mma16816(acc3[mt][nt], al[mt], bh[nt]);
        }
        if (c < 7) {
            asm volatile("cp.async.wait_group %0;" :: "n"(0));
            __syncthreads();                 // next B2/B3 ready; GEMM3 done before H overwrite
        }
    }

    // ---- output: + b2
    #pragma unroll
    for (int mt = 0; mt < 2; mt++)
        #pragma unroll
        for (int nt = 0; nt < 4; nt++) {
            int col = warpN * 32 + nt * 8 + tg * 2;
            float2 bb = *(const float2*)&b2[col];
            #pragma unroll
            for (int h = 0; h < 2; h++) {
                int row = r0 + warpM * 32 + mt * 16 + g + h * 8;
                float2 o = make_float2(acc3[mt][nt][h * 2] + bb.x,
                                       acc3[mt][nt][h * 2 + 1] + bb.y);
                *(float2*)&outf[(size_t)row * HD + col] = o;
            }
        }
}

// ---------------------------------------------------------------------------
extern "C" void kernel_launch(void* const* d_in, const int* in_sizes, int n_in,
                              void* d_out, int out_size) {
    const float* hs     = (const float*)d_in[0];
    const float* Wq     = (const float*)d_in[1];
    const float* coeffs = (const float*)d_in[2];
    const float* W1     = (const float*)d_in[3];
    const float* b1     = (const float*)d_in[4];
    const float* W2     = (const float*)d_in[5];
    const float* b2     = (const float*)d_in[6];
    float* out = (float*)d_out;

    prep_b1eff<<<1, MEMH>>>(W1, b1, coeffs);
    split_hs<<<(TOKENS * HIDDEN / 4) / 256, 256>>>(hs);
    split_wqt<<<(HIDDEN * HIDDEN) / 256, 256>>>(Wq);
    split_w1t<<<(MEMH * KP) / 256, 256>>>(W1);
    split_w2t<<<(HD * MEMH) / 256, 256>>>(W2);

    constexpr int SM1 = (2 * 128 * 20 + 2 * 128 * 20) * 4 * 2;   // 81920 B
    constexpr int SMF = SMEM_FUSED_U32 * 4;                      // 227328 B
    cudaFuncSetAttribute(gemm1_kernel, cudaFuncAttributeMaxDynamicSharedMemorySize, SM1);
    cudaFuncSetAttribute(mlp_fused,    cudaFuncAttributeMaxDynamicSharedMemorySize, SMF);

    gemm1_kernel<<<dim3(TOKENS / 128, HIDDEN / 128), 256, SM1>>>();
    mlp_fused<<<FLATR / 128, 256, SMF>>>(coeffs, b2, out);
}